// round 16
// baseline (speedup 1.0000x reference)
#include <cuda_runtime.h>
#include <math.h>
#include <stdint.h>

#define C_   256
#define G_   16
#define GC_  16
#define P_   9
#define NB_  4
#define H_   64
#define W_   64
#define HW_  (H_*W_)
#define MTOK (NB_*H_*W_)   // 16384
#define HIN_ 66
#define WIN_ 66

// ---- scratch (device globals: zero-initialized at module load) ----
__device__ float g_xt  [MTOK*C_];            // x in NHWC
__device__ float g_xpad[NB_*HIN_*WIN_*C_];   // padded x_proj; border stays 0 forever
__device__ float g_x1  [MTOK*C_];            // dwconv+LN+GELU result (NHWC)
__device__ float g_off [MTOK*G_*P_*2];       // offsets
__device__ float g_mraw[MTOK*G_*P_];         // pre-softmax mask logits
__device__ float g_samp[MTOK*C_];            // sampled output (NHWC)
__device__ float g_tmp [MTOK*C_];            // output proj result (NHWC)

// ---------------- transposes ----------------
__global__ void nchw2nhwc(const float* __restrict__ x, float* __restrict__ y){
    __shared__ float t[32][33];
    int n  = blockIdx.z;
    int c0 = blockIdx.y*32, s0 = blockIdx.x*32;
    const float* xi = x + (size_t)n*C_*HW_;
    float*       yi = y + (size_t)n*HW_*C_;
    #pragma unroll
    for(int i=threadIdx.y;i<32;i+=8)
        t[i][threadIdx.x] = xi[(c0+i)*HW_ + s0 + threadIdx.x];
    __syncthreads();
    #pragma unroll
    for(int i=threadIdx.y;i<32;i+=8)
        yi[(s0+i)*C_ + c0 + threadIdx.x] = t[threadIdx.x][i];
}

__global__ void nhwc2nchw(const float* __restrict__ y, float* __restrict__ x){
    __shared__ float t[32][33];
    int n  = blockIdx.z;
    int c0 = blockIdx.y*32, s0 = blockIdx.x*32;
    const float* yi = y + (size_t)n*HW_*C_;
    float*       xi = x + (size_t)n*C_*HW_;
    #pragma unroll
    for(int i=threadIdx.y;i<32;i+=8)
        t[i][threadIdx.x] = yi[(s0+i)*C_ + c0 + threadIdx.x];
    __syncthreads();
    #pragma unroll
    for(int i=threadIdx.y;i<32;i+=8)
        xi[(c0+i)*HW_ + s0 + threadIdx.x] = t[threadIdx.x][i];
}

// ---------------- tf32 helpers ----------------
__device__ __forceinline__ uint32_t f2tf32(float f){
    uint32_t u;
    asm("cvt.rna.tf32.f32 %0, %1;" : "=r"(u) : "f"(f));
    return u;
}

__device__ __forceinline__ void mma_tf32(float d[4],
                                         uint32_t a0, uint32_t a1, uint32_t a2, uint32_t a3,
                                         uint32_t b0, uint32_t b1){
    asm volatile(
        "mma.sync.aligned.m16n8k8.row.col.f32.tf32.tf32.f32 "
        "{%0,%1,%2,%3}, {%4,%5,%6,%7}, {%8,%9}, {%0,%1,%2,%3};\n"
        : "+f"(d[0]), "+f"(d[1]), "+f"(d[2]), "+f"(d[3])
        : "r"(a0), "r"(a1), "r"(a2), "r"(a3), "r"(b0), "r"(b1));
}

__device__ __forceinline__ void ldsm_x4(uint32_t f[4], uint32_t addr){
    asm volatile("ldmatrix.sync.aligned.m8n8.x4.shared.b16 {%0,%1,%2,%3}, [%4];"
        : "=r"(f[0]), "=r"(f[1]), "=r"(f[2]), "=r"(f[3]) : "r"(addr));
}

// ---------------- tf32 tensor-core GEMM (double-buffered, ldmatrix A) -------
// BM=128 BN=64 BK=32, 256 threads = 8 warps, warp tile 32(M) x 32(N).
// Dynamic smem: 2 x (A 128x36 + B 32x72) tf32 words = 55296 bytes.
#define AS_STRIDE 36
#define BS_STRIDE 72
#define A_WORDS   (128*AS_STRIDE)
#define B_WORDS   (32*BS_STRIDE)
#define GEMM_SMEM ((2*A_WORDS + 2*B_WORDS)*4)

template<bool PADOUT>
__global__ __launch_bounds__(256)
void gemm_tf32(const float* __restrict__ A, const float* __restrict__ B,
               const float* __restrict__ bias, float* __restrict__ Cout, int Ncols){
    extern __shared__ uint32_t sm[];
    uint32_t* Asb[2] = { sm,             sm + A_WORDS };
    uint32_t* Bsb[2] = { sm + 2*A_WORDS, sm + 2*A_WORDS + B_WORDS };

    const int tid  = threadIdx.x;
    const int lane = tid & 31;
    const int warp = tid >> 5;
    const int wm   = warp >> 1;      // 0..3
    const int wn   = warp & 1;       // 0..1
    const int grp  = lane >> 2;      // 0..7
    const int t4   = lane & 3;       // 0..3

    // per-lane ldmatrix tile-row mapping: lanes 0-7 tile0, 8-15 t1, 16-23 t2, 24-31 t3
    const int lt = lane >> 3;        // tile index
    const int lr = lane & 7;         // row within 8x8 tile
    const int a_row_off = ((lt & 1) ? 8 : 0) + lr;   // +8 for tiles 1,3
    const int a_col_off = (lt >= 2) ? 4 : 0;         // +4 words for tiles 2,3

    const int bm0 = blockIdx.y * 128;
    const int bn0 = blockIdx.x * 64;

    float acc[2][4][4];
    #pragma unroll
    for(int mt=0;mt<2;mt++)
        #pragma unroll
        for(int nt=0;nt<4;nt++)
            #pragma unroll
            for(int i=0;i<4;i++) acc[mt][nt][i] = 0.f;

    float4 ra[4];
    float4 rb[2];

    auto ldg = [&](int kk){
        #pragma unroll
        for(int u=0;u<4;u++){
            int f = tid + 256*u;
            int r = f >> 3, c4 = f & 7;
            ra[u] = *(const float4*)&A[(size_t)(bm0+r)*256 + kk + c4*4];
        }
        #pragma unroll
        for(int u=0;u<2;u++){
            int f = tid + 256*u;
            int r = f >> 4, c4 = f & 15;
            int gc = bn0 + c4*4;
            rb[u] = (gc < Ncols) ? *(const float4*)&B[(size_t)(kk+r)*Ncols + gc]
                                 : make_float4(0.f,0.f,0.f,0.f);
        }
    };

    auto sts = [&](uint32_t* As, uint32_t* Bs){
        #pragma unroll
        for(int u=0;u<4;u++){
            int f = tid + 256*u;
            int r = f >> 3, c4 = f & 7;
            *(uint4*)&As[r*AS_STRIDE + c4*4] =
                make_uint4(f2tf32(ra[u].x), f2tf32(ra[u].y), f2tf32(ra[u].z), f2tf32(ra[u].w));
        }
        #pragma unroll
        for(int u=0;u<2;u++){
            int f = tid + 256*u;
            int r = f >> 4, c4 = f & 15;
            *(uint4*)&Bs[r*BS_STRIDE + c4*4] =
                make_uint4(f2tf32(rb[u].x), f2tf32(rb[u].y), f2tf32(rb[u].z), f2tf32(rb[u].w));
        }
    };

    auto comp = [&](const uint32_t* As, const uint32_t* Bs){
        // lane's A-ldmatrix base byte-address for this buffer
        uint32_t a_base0 = (uint32_t)__cvta_generic_to_shared(
            &As[(wm*32 + a_row_off)*AS_STRIDE + a_col_off]);
        #pragma unroll
        for(int ks=0; ks<4; ks++){
            uint32_t afr[2][4];
            #pragma unroll
            for(int mt=0;mt<2;mt++){
                uint32_t addr = a_base0 + (uint32_t)((mt*16*AS_STRIDE + ks*8) * 4);
                ldsm_x4(afr[mt], addr);
            }
            uint32_t bfr[4][2];
            #pragma unroll
            for(int nt=0;nt<4;nt++){
                int cn = wn*32 + nt*8 + grp;
                bfr[nt][0] = Bs[(ks*8 + t4    )*BS_STRIDE + cn];
                bfr[nt][1] = Bs[(ks*8 + t4 + 4)*BS_STRIDE + cn];
            }
            #pragma unroll
            for(int mt=0;mt<2;mt++)
                #pragma unroll
                for(int nt=0;nt<4;nt++)
                    mma_tf32(acc[mt][nt], afr[mt][0], afr[mt][1], afr[mt][2], afr[mt][3],
                             bfr[nt][0], bfr[nt][1]);
        }
    };

    // prologue
    ldg(0);
    sts(Asb[0], Bsb[0]);
    __syncthreads();

    #pragma unroll
    for(int t=0; t<8; t++){
        if(t < 7) ldg((t+1)*32);            // prefetch next tile (overlaps compute)
        comp(Asb[t&1], Bsb[t&1]);
        if(t < 7){
            sts(Asb[(t+1)&1], Bsb[(t+1)&1]);
            __syncthreads();
        }
    }

    // epilogue: c0,c1 -> (row, col..col+1); c2,c3 -> (row+8, col..col+1)
    #pragma unroll
    for(int mt=0;mt<2;mt++){
        int r0 = bm0 + wm*32 + mt*16 + grp;
        #pragma unroll
        for(int nt=0;nt<4;nt++){
            int col = bn0 + wn*32 + nt*8 + t4*2;
            if(col >= Ncols) continue;
            float2 bb = *(const float2*)&bias[col];
            float2 v0 = make_float2(acc[mt][nt][0]+bb.x, acc[mt][nt][1]+bb.y);
            float2 v1 = make_float2(acc[mt][nt][2]+bb.x, acc[mt][nt][3]+bb.y);
            if(PADOUT){
                int n0 = r0 >> 12, h0 = (r0 >> 6) & 63, w0 = r0 & 63;
                int r1 = r0 + 8;
                int n1 = r1 >> 12, h1 = (r1 >> 6) & 63, w1 = r1 & 63;
                *(float2*)&g_xpad[ ((size_t)(n0*HIN_ + h0+1)*WIN_ + (w0+1))*C_ + col ] = v0;
                *(float2*)&g_xpad[ ((size_t)(n1*HIN_ + h1+1)*WIN_ + (w1+1))*C_ + col ] = v1;
            }else{
                *(float2*)&Cout[(size_t)r0*Ncols + col]     = v0;
                *(float2*)&Cout[(size_t)(r0+8)*Ncols + col] = v1;
            }
        }
    }
}

// ---------------- depthwise 3x3 + LayerNorm + exact GELU ----------------
__global__ __launch_bounds__(256)
void dwln(const float* __restrict__ xt, const float* __restrict__ dww,
          const float* __restrict__ dwb, const float* __restrict__ lng,
          const float* __restrict__ lnb, float* __restrict__ x1){
    int tok = blockIdx.x;
    int c   = threadIdx.x;
    int n = tok >> 12, h = (tok >> 6) & 63, w = tok & 63;
    float acc = dwb[c];
    #pragma unroll
    for(int ky=0;ky<3;ky++){
        int yy = h + ky - 1;
        if(yy < 0 || yy >= H_) continue;
        #pragma unroll
        for(int kx=0;kx<3;kx++){
            int xx = w + kx - 1;
            if(xx < 0 || xx >= W_) continue;
            acc += xt[((size_t)n*HW_ + yy*W_ + xx)*C_ + c] * dww[c*9 + ky*3 + kx];
        }
    }
    __shared__ float rs[8], rq[8];
    float s1 = acc, s2 = acc*acc;
    #pragma unroll
    for(int o=16;o;o>>=1){
        s1 += __shfl_xor_sync(0xffffffffu, s1, o);
        s2 += __shfl_xor_sync(0xffffffffu, s2, o);
    }
    int lane = c & 31, wid = c >> 5;
    if(lane == 0){ rs[wid] = s1; rq[wid] = s2; }
    __syncthreads();
    float S1 = 0.f, S2 = 0.f;
    #pragma unroll
    for(int i=0;i<8;i++){ S1 += rs[i]; S2 += rq[i]; }
    float mean = S1 * (1.0f/256.0f);
    float var  = S2 * (1.0f/256.0f) - mean*mean;
    float rstd = rsqrtf(var + 1e-5f);
    float v = (acc - mean) * rstd * lng[c] + lnb[c];
    float gv = 0.5f * v * (1.0f + erff(v * 0.70710678118654752440f));
    x1[(size_t)tok*C_ + c] = gv;
}

// ---------------- deformable bilinear sampling (softmax fused, float4) ------
__device__ __forceinline__ float4 fetch4(const float* __restrict__ base, int y, int x){
    if(y < 0 || y >= HIN_ || x < 0 || x >= WIN_) return make_float4(0.f,0.f,0.f,0.f);
    return *(const float4*)&base[((size_t)y*WIN_ + x)*C_];
}

__global__ __launch_bounds__(256)
void dcn_sample(const float* __restrict__ xpad, const float* __restrict__ off,
                const float* __restrict__ mraw, float* __restrict__ out){
    int tid = threadIdx.x;
    int tok = blockIdx.x*4 + (tid >> 6);
    int t64 = tid & 63;
    int g   = t64 >> 2;          // 16 groups
    int cq  = t64 & 3;           // 4 channel-quads per group
    int n = tok >> 12, h = (tok >> 6) & 63, w = tok & 63;
    const float* o = off  + (size_t)tok*(G_*P_*2) + g*(P_*2);
    const float* m = mraw + (size_t)tok*(G_*P_)   + g*P_;
    const float* base = xpad + (size_t)n*HIN_*WIN_*C_ + g*GC_ + cq*4;

    // inline softmax over 9 logits (redundant per 4 lanes of a group)
    float mv[P_], mx = -1e30f;
    #pragma unroll
    for(int p=0;p<P_;p++){ mv[p] = m[p]; mx = fmaxf(mx, mv[p]); }
    float ssum = 0.f;
    #pragma unroll
    for(int p=0;p<P_;p++){ mv[p] = expf(mv[p]-mx); ssum += mv[p]; }
    float sinv = 1.0f/ssum;

    float4 acc = make_float4(0.f,0.f,0.f,0.f);
    #pragma unroll
    for(int p=0;p<P_;p++){
        float ox = o[p*2], oy = o[p*2+1];
        float px = (float)(w + (p/3)) + ox;
        float py = (float)(h + (p%3)) + oy;
        float fx = floorf(px), fy = floorf(py);
        int x0 = (int)fx, y0 = (int)fy;
        float wx = px - fx, wy = py - fy;
        float mp = mv[p]*sinv;
        float w00 = (1.f-wy)*(1.f-wx)*mp;
        float w01 = (1.f-wy)*wx*mp;
        float w10 = wy*(1.f-wx)*mp;
        float w11 = wy*wx*mp;
        float4 v00 = fetch4(base, y0,   x0  );
        float4 v01 = fetch4(base, y0,   x0+1);
        float4 v10 = fetch4(base, y0+1, x0  );
        float4 v11 = fetch4(base, y0+1, x0+1);
        acc.x += v00.x*w00 + v01.x*w01 + v10.x*w10 + v11.x*w11;
        acc.y += v00.y*w00 + v01.y*w01 + v10.y*w10 + v11.y*w11;
        acc.z += v00.z*w00 + v01.z*w01 + v10.z*w10 + v11.z*w11;
        acc.w += v00.w*w00 + v01.w*w01 + v10.w*w10 + v11.w*w11;
    }
    *(float4*)&out[(size_t)tok*C_ + g*GC_ + cq*4] = acc;
}

// ---------------- launch ----------------
extern "C" void kernel_launch(void* const* d_in, const int* in_sizes, int n_in,
                              void* d_out, int out_size){
    const float* x      = (const float*)d_in[0];
    const float* dw_w   = (const float*)d_in[1];
    const float* dw_b   = (const float*)d_in[2];
    const float* ln_g   = (const float*)d_in[3];
    const float* ln_b   = (const float*)d_in[4];
    const float* off_w  = (const float*)d_in[5];
    const float* off_b  = (const float*)d_in[6];
    const float* mask_w = (const float*)d_in[7];
    const float* mask_b = (const float*)d_in[8];
    const float* inp_w  = (const float*)d_in[9];
    const float* inp_b  = (const float*)d_in[10];
    const float* out_w  = (const float*)d_in[11];
    const float* out_b  = (const float*)d_in[12];
    float* out = (float*)d_out;

    float *xt, *xpad, *x1, *off, *mraw, *samp, *tmp;
    cudaGetSymbolAddress((void**)&xt,   g_xt);
    cudaGetSymbolAddress((void**)&xpad, g_xpad);
    cudaGetSymbolAddress((void**)&x1,   g_x1);
    cudaGetSymbolAddress((void**)&off,  g_off);
    cudaGetSymbolAddress((void**)&mraw, g_mraw);
    cudaGetSymbolAddress((void**)&samp, g_samp);
    cudaGetSymbolAddress((void**)&tmp,  g_tmp);

    // allow 55KB dynamic smem for the GEMMs (host-side attr set; capture-safe)
    cudaFuncSetAttribute(gemm_tf32<true>,  cudaFuncAttributeMaxDynamicSharedMemorySize, GEMM_SMEM);
    cudaFuncSetAttribute(gemm_tf32<false>, cudaFuncAttributeMaxDynamicSharedMemorySize, GEMM_SMEM);

    // 1) NCHW -> NHWC
    nchw2nhwc<<<dim3(HW_/32, C_/32, NB_), dim3(32,8)>>>(x, xt);

    // 2) input projection -> padded buffer interior (border stays 0)
    gemm_tf32<true><<<dim3(C_/64, MTOK/128), 256, GEMM_SMEM>>>(xt, inp_w, inp_b, xpad, C_);

    // 3) depthwise conv + LN + GELU
    dwln<<<MTOK, 256>>>(xt, dw_w, dw_b, ln_g, ln_b, x1);

    // 4) offset GEMM (N=288)
    gemm_tf32<false><<<dim3((288+63)/64, MTOK/128), 256, GEMM_SMEM>>>(x1, off_w, off_b, off, 288);

    // 5) mask GEMM (N=144)  (softmax fused into sampling)
    gemm_tf32<false><<<dim3((144+63)/64, MTOK/128), 256, GEMM_SMEM>>>(x1, mask_w, mask_b, mraw, 144);

    // 6) deformable sampling (+ inline softmax), 4 tokens per block
    dcn_sample<<<MTOK/4, 256>>>(xpad, off, mraw, samp);

    // 7) output projection
    gemm_tf32<false><<<dim3(C_/64, MTOK/128), 256, GEMM_SMEM>>>(samp, out_w, out_b, tmp, C_);

    // 8) NHWC -> NCHW into d_out
    nhwc2nchw<<<dim3(HW_/32, C_/32, NB_), dim3(32,8)>>>(tmp, out);
}